// round 3
// baseline (speedup 1.0000x reference)
#include <cuda_runtime.h>
#include <math.h>

// Problem dims
#define B_    32
#define E_    64
#define R_    36
#define D_    512
#define DT_   768
#define DI_   2048
#define TROWS 2048   // B*E
#define IROWS 1152   // B*R
#define SHI_S 516    // padded smem row stride (floats) for conflict-free LDS

// Scratch (device globals; no allocation allowed)
__device__ float g_T [TROWS*D_];
__device__ float g_I [IROWS*D_];
__device__ float g_HT[TROWS*D_];
__device__ float g_HI[IROWS*D_];
__device__ float g_te[TROWS];
__device__ float g_ur[IROWS];

// ---------- packed f32x2 helpers (sm_100+) ----------
static __device__ __forceinline__ unsigned long long f2add(unsigned long long a, unsigned long long b){
    unsigned long long r; asm("add.rn.f32x2 %0, %1, %2;" : "=l"(r) : "l"(a), "l"(b)); return r;
}
static __device__ __forceinline__ unsigned long long f2fma(unsigned long long a, unsigned long long b, unsigned long long c){
    unsigned long long r; asm("fma.rn.f32x2 %0, %1, %2, %3;" : "=l"(r) : "l"(a), "l"(b), "l"(c)); return r;
}
static __device__ __forceinline__ unsigned long long pk2(float x, float y){
    unsigned long long r; asm("mov.b64 %0, {%1, %2};" : "=l"(r) : "f"(x), "f"(y)); return r;
}
static __device__ __forceinline__ float2 upk2(unsigned long long v){
    float2 f; asm("mov.b64 {%0, %1}, %2;" : "=f"(f.x), "=f"(f.y) : "l"(v)); return f;
}

// ---------- GEMM: C[M,512] = op(A[M,K] @ W[K,512] (+bias) (relu)) ----------
// BM=64, BN=64, BK=16, 256 threads, 4x4 outputs/thread, f32x2 accumulation,
// double-buffered global->reg prefetch. M%64==0, K%16==0 (true for all calls).
template<bool RELU, bool BIAS>
__global__ __launch_bounds__(256) void gemm_k(const float* __restrict__ A,
                                              const float* __restrict__ W,
                                              const float* __restrict__ bias,
                                              float* __restrict__ C,
                                              int M, int K)
{
    const int N = 512;
    __shared__ float4 As4[64][4];    // [m][k4] natural layout
    __shared__ float4 Bs4[16][16];   // [k][n4]

    const int tid = threadIdx.x;
    const int tx = tid & 15, ty = tid >> 4;
    const int m0 = blockIdx.y * 64, n0 = blockIdx.x * 64;
    const int aRow = tid >> 2, aC4 = tid & 3;
    const int bRow = tid >> 4, bC4 = tid & 15;

    unsigned long long acc[4][2] = {};

    const float* Ab = A + (m0 + aRow) * K + aC4 * 4;
    const float* Wb = W + bRow * N + n0 + bC4 * 4;

    float4 aReg = *reinterpret_cast<const float4*>(Ab);
    float4 bReg = *reinterpret_cast<const float4*>(Wb);

    for (int k0 = 0; k0 < K; k0 += 16) {
        As4[aRow][aC4] = aReg;
        Bs4[bRow][bC4] = bReg;
        __syncthreads();
        if (k0 + 16 < K) {
            aReg = *reinterpret_cast<const float4*>(Ab + k0 + 16);
            bReg = *reinterpret_cast<const float4*>(Wb + (k0 + 16) * N);
        }
        const float* As = &As4[0][0].x;
        #pragma unroll
        for (int k = 0; k < 16; ++k) {
            ulonglong2 b = *reinterpret_cast<const ulonglong2*>(&Bs4[k][tx]);
            #pragma unroll
            for (int m = 0; m < 4; ++m) {
                float a = As[(ty * 4 + m) * 16 + k];
                unsigned long long am = pk2(a, a);
                acc[m][0] = f2fma(am, b.x, acc[m][0]);
                acc[m][1] = f2fma(am, b.y, acc[m][1]);
            }
        }
        __syncthreads();
    }

    float4 bv = make_float4(0.f, 0.f, 0.f, 0.f);
    if (BIAS) bv = *reinterpret_cast<const float4*>(bias + n0 + tx * 4);
    #pragma unroll
    for (int m = 0; m < 4; ++m) {
        float2 c01 = upk2(acc[m][0]);
        float2 c23 = upk2(acc[m][1]);
        float4 o;
        o.x = c01.x + bv.x; o.y = c01.y + bv.y;
        o.z = c23.x + bv.z; o.w = c23.y + bv.w;
        if (RELU) {
            o.x = fmaxf(o.x, 0.f); o.y = fmaxf(o.y, 0.f);
            o.z = fmaxf(o.z, 0.f); o.w = fmaxf(o.w, 0.f);
        }
        *reinterpret_cast<float4*>(C + (m0 + ty * 4 + m) * N + n0 + tx * 4) = o;
    }
}

// ---------- LayerNorm in place over rows of 512 ----------
__global__ __launch_bounds__(128) void ln_k(float* __restrict__ X,
                                            const float* __restrict__ g,
                                            const float* __restrict__ beta)
{
    const int row = blockIdx.x;
    const int tid = threadIdx.x;
    float4 v = reinterpret_cast<float4*>(X + row * D_)[tid];
    float s  = v.x + v.y + v.z + v.w;
    float ss = v.x * v.x + v.y * v.y + v.z * v.z + v.w * v.w;
    #pragma unroll
    for (int o = 16; o; o >>= 1) {
        s  += __shfl_xor_sync(0xffffffffu, s,  o);
        ss += __shfl_xor_sync(0xffffffffu, ss, o);
    }
    __shared__ float rs[4], rss[4];
    int w = tid >> 5, l = tid & 31;
    if (l == 0) { rs[w] = s; rss[w] = ss; }
    __syncthreads();
    s  = rs[0] + rs[1] + rs[2] + rs[3];
    ss = rss[0] + rss[1] + rss[2] + rss[3];
    float mu   = s * (1.f / D_);
    float var  = ss * (1.f / D_) - mu * mu;
    float rstd = rsqrtf(var + 1e-5f);
    float4 gg = reinterpret_cast<const float4*>(g)[tid];
    float4 bb = reinterpret_cast<const float4*>(beta)[tid];
    v.x = (v.x - mu) * rstd * gg.x + bb.x;
    v.y = (v.y - mu) * rstd * gg.y + bb.y;
    v.z = (v.z - mu) * rstd * gg.z + bb.z;
    v.w = (v.w - mu) * rstd * gg.w + bb.w;
    reinterpret_cast<float4*>(X + row * D_)[tid] = v;
}

// ---------- per-row dot with W2: out[row] = H[row,:] . w2 ----------
__global__ __launch_bounds__(256) void dotw2_k(const float* __restrict__ H,
                                               const float* __restrict__ w2,
                                               float* __restrict__ out, int rows)
{
    const int w = threadIdx.x >> 5, l = threadIdx.x & 31;
    const int row = blockIdx.x * 8 + w;
    if (row >= rows) return;
    const float4* h4 = reinterpret_cast<const float4*>(H + row * D_);
    const float4* w4 = reinterpret_cast<const float4*>(w2);
    float s = 0.f;
    #pragma unroll
    for (int i = 0; i < 4; ++i) {
        float4 a = h4[l + i * 32];
        float4 b = w4[l + i * 32];
        s += a.x * b.x + a.y * b.y + a.z * b.z + a.w * b.w;
    }
    #pragma unroll
    for (int o = 16; o; o >>= 1) s += __shfl_xor_sync(0xffffffffu, s, o);
    if (l == 0) out[row] = s;
}

// ---------- fused pairwise score kernel ----------
// score[b,e,r] = sigmoid( 0.5*(te[e] + ur[r] + sum_d |ht+hi| * w2) + b2 )
// grid (32, 16): one batch x 4-e tile per block; 160 threads = 4 d-quarters x 36 r
// (+16 spares). hi tile lives in smem with 516-float row stride (bank spread).
#define OFF_HI  0
#define OFF_HT  (R_ * SHI_S)                  // 18576
#define OFF_W2  (OFF_HT + 4 * D_)             // 20624
#define OFF_RED (OFF_W2 + D_)                 // 21136
#define OFF_UR  (OFF_RED + 4 * 160)           // 21776
#define OFF_TE  (OFF_UR + R_)                 // 21812
#define SCORE_SMEM ((OFF_TE + 4) * 4)         // 87264 bytes

__global__ __launch_bounds__(160) void score_k(const float* __restrict__ W2,
                                               const float* __restrict__ b2p,
                                               float* __restrict__ out)
{
    extern __shared__ float sm[];
    const int b = blockIdx.x, e0 = blockIdx.y * 4;
    const int tid = threadIdx.x;

    // cooperative loads
    {
        const float4* src = reinterpret_cast<const float4*>(g_HI + b * R_ * D_);
        for (int i = tid; i < R_ * (D_ / 4); i += 160) {
            int row = i >> 7, c = i & 127;
            reinterpret_cast<float4*>(sm + OFF_HI + row * SHI_S)[c] = src[i];
        }
        const float4* srcT = reinterpret_cast<const float4*>(g_HT + (b * E_ + e0) * D_);
        for (int i = tid; i < 4 * (D_ / 4); i += 160)
            reinterpret_cast<float4*>(sm + OFF_HT)[i] = srcT[i];
        const float4* srcW = reinterpret_cast<const float4*>(W2);
        for (int i = tid; i < D_ / 4; i += 160)
            reinterpret_cast<float4*>(sm + OFF_W2)[i] = srcW[i];
        if (tid < R_) sm[OFF_UR + tid] = g_ur[b * R_ + tid];
        if (tid < 4)  sm[OFF_TE + tid] = g_te[b * E_ + e0 + tid];
    }
    __syncthreads();

    int q4 = tid / 36;
    int r  = tid - q4 * 36;
    int q  = q4 < 3 ? q4 : 3;

    const ulonglong2* hp = reinterpret_cast<const ulonglong2*>(sm + OFF_HI + r * SHI_S + q * 128);
    const ulonglong2* wp = reinterpret_cast<const ulonglong2*>(sm + OFF_W2 + q * 128);
    const ulonglong2* tp = reinterpret_cast<const ulonglong2*>(sm + OFF_HT + q * 128);

    const unsigned long long ABSM = 0x7FFFFFFF7FFFFFFFull;
    unsigned long long a0 = 0, a1 = 0, a2 = 0, a3 = 0;

    #pragma unroll 8
    for (int j = 0; j < 32; ++j) {
        ulonglong2 h = hp[j];
        ulonglong2 w = wp[j];
        ulonglong2 t;
        t = tp[j];
        a0 = f2fma(f2add(t.x, h.x) & ABSM, w.x, a0);
        a0 = f2fma(f2add(t.y, h.y) & ABSM, w.y, a0);
        t = tp[128 + j];
        a1 = f2fma(f2add(t.x, h.x) & ABSM, w.x, a1);
        a1 = f2fma(f2add(t.y, h.y) & ABSM, w.y, a1);
        t = tp[256 + j];
        a2 = f2fma(f2add(t.x, h.x) & ABSM, w.x, a2);
        a2 = f2fma(f2add(t.y, h.y) & ABSM, w.y, a2);
        t = tp[384 + j];
        a3 = f2fma(f2add(t.x, h.x) & ABSM, w.x, a3);
        a3 = f2fma(f2add(t.y, h.y) & ABSM, w.y, a3);
    }

    float2 p;
    p = upk2(a0); sm[OFF_RED + 0 * 160 + tid] = p.x + p.y;
    p = upk2(a1); sm[OFF_RED + 1 * 160 + tid] = p.x + p.y;
    p = upk2(a2); sm[OFF_RED + 2 * 160 + tid] = p.x + p.y;
    p = upk2(a3); sm[OFF_RED + 3 * 160 + tid] = p.x + p.y;
    __syncthreads();

    if (tid < R_) {
        float b2v = b2p[0];
        float ur  = sm[OFF_UR + tid];
        #pragma unroll
        for (int e = 0; e < 4; ++e) {
            const float* rd = sm + OFF_RED + e * 160;
            float S = rd[tid] + rd[36 + tid] + rd[72 + tid] + rd[108 + tid];
            float raw = 0.5f * (sm[OFF_TE + e] + ur + S) + b2v;
            out[b * (E_ * R_) + (e0 + e) * R_ + tid] = 1.0f / (1.0f + expf(-raw));
        }
    }
}

// ---------- softmax over E*R per batch + weighted aggregation ----------
__global__ __launch_bounds__(256) void softagg_k(const float* __restrict__ sc,
                                                 float* __restrict__ out)
{
    __shared__ float s[E_ * R_];
    __shared__ float red[8];
    __shared__ float wr[R_];
    const int b = blockIdx.x, tid = threadIdx.x;
    const int lane = tid & 31, w = tid >> 5;

    float mx = -1e30f;
    for (int i = tid; i < E_ * R_; i += 256) {
        float v = sc[b * E_ * R_ + i];
        s[i] = v;
        mx = fmaxf(mx, v);
    }
    #pragma unroll
    for (int o = 16; o; o >>= 1) mx = fmaxf(mx, __shfl_xor_sync(0xffffffffu, mx, o));
    if (lane == 0) red[w] = mx;
    __syncthreads();
    float m = red[0];
    #pragma unroll
    for (int k = 1; k < 8; ++k) m = fmaxf(m, red[k]);
    __syncthreads();

    float sum = 0.f;
    for (int i = tid; i < E_ * R_; i += 256) {
        float e2 = expf(s[i] - m);
        s[i] = e2;
        sum += e2;
    }
    #pragma unroll
    for (int o = 16; o; o >>= 1) sum += __shfl_xor_sync(0xffffffffu, sum, o);
    if (lane == 0) red[w] = sum;
    __syncthreads();
    float Z = 0.f;
    #pragma unroll
    for (int k = 0; k < 8; ++k) Z += red[k];
    float scale = 1.0f / (Z * (float)E_);

    if (tid < R_) {
        float a = 0.f;
        for (int e = 0; e < E_; ++e) a += s[e * R_ + tid];
        wr[tid] = a * scale;
    }
    __syncthreads();

    for (int d = tid; d < D_; d += 256) {
        float a = 0.f;
        #pragma unroll
        for (int r2 = 0; r2 < R_; ++r2)
            a += wr[r2] * g_I[(b * R_ + r2) * D_ + d];
        out[B_ * E_ * R_ + b * D_ + d] = a;
    }
}

// ---------- launch ----------
extern "C" void kernel_launch(void* const* d_in, const int* in_sizes, int n_in,
                              void* d_out, int out_size)
{
    (void)in_sizes; (void)n_in; (void)out_size;
    const float* text      = (const float*)d_in[0];
    const float* image     = (const float*)d_in[1];
    const float* W_text    = (const float*)d_in[2];
    const float* b_text    = (const float*)d_in[3];
    const float* g_text    = (const float*)d_in[4];
    const float* beta_text = (const float*)d_in[5];
    const float* W_img     = (const float*)d_in[6];
    const float* b_img     = (const float*)d_in[7];
    const float* g_img     = (const float*)d_in[8];
    const float* beta_img  = (const float*)d_in[9];
    const float* W1        = (const float*)d_in[10];
    const float* b1        = (const float*)d_in[11];
    const float* W2        = (const float*)d_in[12];
    const float* b2        = (const float*)d_in[13];
    float* out = (float*)d_out;

    void* p;
    cudaGetSymbolAddress(&p, g_T);  float* T  = (float*)p;
    cudaGetSymbolAddress(&p, g_I);  float* I  = (float*)p;
    cudaGetSymbolAddress(&p, g_HT); float* HT = (float*)p;
    cudaGetSymbolAddress(&p, g_HI); float* HI = (float*)p;
    cudaGetSymbolAddress(&p, g_te); float* te = (float*)p;
    cudaGetSymbolAddress(&p, g_ur); float* ur = (float*)p;

    dim3 blk(256);
    dim3 gT(8, TROWS / 64);  // 8 x 32
    dim3 gI(8, IROWS / 64);  // 8 x 18

    gemm_k<true,  true ><<<gT, blk>>>(text,  W_text, b_text, T,  TROWS, DT_);
    gemm_k<true,  true ><<<gI, blk>>>(image, W_img,  b_img,  I,  IROWS, DI_);
    ln_k<<<TROWS, 128>>>(T, g_text, beta_text);
    ln_k<<<IROWS, 128>>>(I, g_img,  beta_img);
    gemm_k<false, false><<<gT, blk>>>(T, W1,            nullptr, HT, TROWS, D_);
    gemm_k<false, true ><<<gI, blk>>>(I, W1 + D_ * D_,  b1,      HI, IROWS, D_);
    dotw2_k<<<TROWS / 8, 256>>>(HT, W2, te, TROWS);
    dotw2_k<<<IROWS / 8, 256>>>(HI, W2, ur, IROWS);

    cudaFuncSetAttribute(score_k, cudaFuncAttributeMaxDynamicSharedMemorySize, SCORE_SMEM);
    score_k<<<dim3(B_, 16), 160, SCORE_SMEM>>>(W2, b2, out);
    softagg_k<<<B_, 256>>>(out, out);
}